// round 1
// baseline (speedup 1.0000x reference)
#include <cuda_runtime.h>
#include <cstdint>

// Problem constants
#define NB   4
#define CC   64
#define HH   256
#define WW   448
#define HWSZ (HH * WW)            // 114688
#define NPIX (NB * HWSZ)          // 458752
#define CP   68                   // 64 ch + 1 norm, padded to 68 for 16B alignment

// Scratch accumulator, channel-last: [n][h][w][CP]
__device__ float g_accum[(size_t)NPIX * CP];

// ---------------------------------------------------------------------------
// Kernel 1: zero the accumulator (float4 stores)
// ---------------------------------------------------------------------------
__global__ void zero_kernel() {
    size_t i = (size_t)blockIdx.x * blockDim.x + threadIdx.x;
    float4* p = reinterpret_cast<float4*>(g_accum);
    p[i] = make_float4(0.f, 0.f, 0.f, 0.f);
}

// ---------------------------------------------------------------------------
// Kernel 2: splat. One block = 32 consecutive pixels (same n, h row).
// 256 threads. Coalesced NCHW input reads staged through smem, then
// vector red.global.add.v4.f32 into channel-last accumulator.
// ---------------------------------------------------------------------------
__global__ __launch_bounds__(256) void splat_kernel(
    const float* __restrict__ inp,
    const float* __restrict__ flow,
    const float* __restrict__ metric)
{
    __shared__ float s_in[32][33];     // 32 channels x 32 pixels (+pad)
    __shared__ int   s_base[32][4];    // accum base offset per corner
    __shared__ float s_wgt[32][4];     // bilinear weight per corner (0 if invalid)
    __shared__ float s_m[32];          // exp(metric)

    const int tid  = threadIdx.x;
    const int p0   = blockIdx.x * 32;  // W%32==0 -> block never straddles a row

    if (tid < 32) {
        int p   = p0 + tid;
        int n   = p / HWSZ;
        int rem = p - n * HWSZ;
        int h   = rem / WW;
        int w   = rem - h * WW;

        float fx = flow[(size_t)n * 2 * HWSZ + rem];
        float fy = flow[(size_t)n * 2 * HWSZ + HWSZ + rem];
        float m  = expf(metric[(size_t)n * HWSZ + rem]);

        float xx = (float)w + fx;
        float yy = (float)h + fy;
        float x0f = floorf(xx);
        float y0f = floorf(yy);
        int x0 = (int)x0f;
        int y0 = (int)y0f;
        float ax = xx - x0f;           // in [0,1)
        float ay = yy - y0f;

        float wgt[4];
        wgt[0] = (1.f - ax) * (1.f - ay);  // (x0, y0)
        wgt[1] = ax * (1.f - ay);          // (x1, y0)
        wgt[2] = (1.f - ax) * ay;          // (x0, y1)
        wgt[3] = ax * ay;                  // (x1, y1)

        #pragma unroll
        for (int j = 0; j < 4; j++) {
            int xi = x0 + (j & 1);
            int yi = y0 + (j >> 1);
            bool valid = ((unsigned)xi < (unsigned)WW) && ((unsigned)yi < (unsigned)HH);
            s_base[tid][j] = valid ? (n * HWSZ + yi * WW + xi) * CP : 0;
            s_wgt[tid][j]  = valid ? wgt[j] : 0.f;
        }
        s_m[tid] = m;
    }
    __syncthreads();

    const int lane = tid & 31;
    const int wa   = tid >> 5;         // 8 warps

    const int n0   = p0 / HWSZ;
    const int rem0 = p0 - n0 * HWSZ;
    const float* ibase = inp + (size_t)n0 * CC * HWSZ + rem0;

    const float m = s_m[lane];

    #pragma unroll
    for (int c0 = 0; c0 < CC; c0 += 32) {
        // Stage 32 channels x 32 pixels, coalesced (lanes across w)
        #pragma unroll
        for (int k = 0; k < 4; k++) {
            int cr = wa + k * 8;       // 0..31
            s_in[cr][lane] = ibase[(size_t)(c0 + cr) * HWSZ + lane];
        }
        __syncthreads();

        // This thread: pixel = lane, channels c0 + wa*4 .. +3
        float4 v;
        v.x = s_in[wa * 4 + 0][lane] * m;
        v.y = s_in[wa * 4 + 1][lane] * m;
        v.z = s_in[wa * 4 + 2][lane] * m;
        v.w = s_in[wa * 4 + 3][lane] * m;

        #pragma unroll
        for (int j = 0; j < 4; j++) {
            float wg = s_wgt[lane][j];
            if (wg != 0.f) {
                float* addr = g_accum + s_base[lane][j] + c0 + wa * 4;
                asm volatile(
                    "red.global.add.v4.f32 [%0], {%1, %2, %3, %4};"
                    :: "l"(addr), "f"(v.x * wg), "f"(v.y * wg),
                       "f"(v.z * wg), "f"(v.w * wg)
                    : "memory");
            }
        }
        __syncthreads();
    }

    // Norm channel (index 64), one lane per pixel
    if (tid < 32) {
        float mm = s_m[tid];
        #pragma unroll
        for (int j = 0; j < 4; j++) {
            float wg = s_wgt[tid][j];
            if (wg != 0.f) {
                atomicAdd(g_accum + s_base[tid][j] + 64, mm * wg);
            }
        }
    }
}

// ---------------------------------------------------------------------------
// Kernel 3: normalize. One block = 32 pixels, stage accum through smem
// (coalesced), write NCHW output coalesced.
// ---------------------------------------------------------------------------
__global__ __launch_bounds__(256) void norm_kernel(float* __restrict__ out)
{
    __shared__ float s_acc[32 * CP];   // 8704 B

    const int tid = threadIdx.x;
    const int p0  = blockIdx.x * 32;

    const float* abase = g_accum + (size_t)p0 * CP;
    #pragma unroll
    for (int i = tid; i < 32 * CP; i += 256) s_acc[i] = abase[i];
    __syncthreads();

    const int lane = tid & 31;
    const int wa   = tid >> 5;

    const int n0   = p0 / HWSZ;
    const int rem0 = p0 - n0 * HWSZ;
    float* obase = out + (size_t)n0 * CC * HWSZ + rem0;

    float nm  = s_acc[lane * CP + 64];
    float inv = (nm == 0.f) ? 1.f : (1.f / nm);

    #pragma unroll
    for (int k = 0; k < 8; k++) {
        int c = wa + k * 8;
        obase[(size_t)c * HWSZ + lane] = s_acc[lane * CP + c] * inv;
    }
}

// ---------------------------------------------------------------------------
extern "C" void kernel_launch(void* const* d_in, const int* in_sizes, int n_in,
                              void* d_out, int out_size)
{
    const float* inp    = (const float*)d_in[0];
    const float* flow   = (const float*)d_in[1];
    const float* metric = (const float*)d_in[2];
    float* out = (float*)d_out;

    // total accum floats = NPIX*CP = 31,195,136 -> /4 = 7,798,784 float4
    zero_kernel<<<7798784 / 256, 256>>>();
    splat_kernel<<<NPIX / 32, 256>>>(inp, flow, metric);
    norm_kernel<<<NPIX / 32, 256>>>(out);
}